// round 4
// baseline (speedup 1.0000x reference)
#include <cuda_runtime.h>
#include <cuda_bf16.h>

// ---------------------------------------------------------------------------
// Attention_26379689132660
//
// Reference computes, per spatial position (b, h, w):
//   x_t = W_in z_t + b_in           (t = 0..7, z_t in R^3, x in R^32)
//   q = Wq x_7 + bq ; k_t = Wk x_t + bk ; v_t = Wv x_t + bv
//   4 heads of dk=8 attention over t, only query t=7 kept
//   out = W_o (attn output) + b_o   (3 channels)
//
// Everything is affine in z_t, so we fold:
//   A_X = W_X @ W_in (32x3), c_X = W_X b_in + b_X          (X in {q,k,v})
//   score_h(t) = scale * ( z7^T M_h z_t + u_h.z_t + r_h.z7 + e_h )
//     M_h[a][b] = sum_{d in head} A_q[d][a] A_k[d][b]   (3x3)
//     u_h[b]    = sum_d c_q[d] A_k[d][b]
//     r_h[a]    = sum_d A_q[d][a] c_k[d]
//     e_h       = sum_d c_q[d] c_k[d]
//   out[o] = b_o[o] + sum_h ( G_h[o] . zbar_h + g_h[o] )
//     G_h[o][c] = sum_{d in head} W_o[o][d] A_v[d][c]    (3x3)
//     g_h[o]    = sum_d W_o[o][d] c_v[d]
//     zbar_h    = sum_t softmax_w[t] * z_t   (softmax weights sum to 1)
//
// Per-position cost collapses to ~350 FMAs + 32 exps. Memory bound (~28 MB).
// ---------------------------------------------------------------------------

struct DerivedParams {
    float M[4][3][3];   // per-head bilinear score matrix
    float u[4][3];
    float r[4][3];
    float e[4];
    float G[4][3][3];   // per-head fused output matrix
    float g[4][3];
    float bo[3];
};
// 115 floats total

__device__ float g_A[3][32][3];   // A_q, A_k, A_v
__device__ float g_c[3][32];      // c_q, c_k, c_v
__device__ DerivedParams g_P;

// One block, 128 threads. Tiny.
__global__ void precompute_kernel(
    const float* __restrict__ W_in, const float* __restrict__ b_in,
    const float* __restrict__ W_q,  const float* __restrict__ b_q,
    const float* __restrict__ W_k,  const float* __restrict__ b_k,
    const float* __restrict__ W_v,  const float* __restrict__ b_v,
    const float* __restrict__ W_o,  const float* __restrict__ b_o)
{
    const int tid = threadIdx.x;
    const float* Wx[3] = {W_q, W_k, W_v};
    const float* bx[3] = {b_q, b_k, b_v};

    // Stage 1: A_X[d][c] = sum_i W_X[d][i] * W_in[i][c]   (288 entries)
    for (int idx = tid; idx < 288; idx += blockDim.x) {
        int X = idx / 96, rem = idx % 96, d = rem / 3, c = rem % 3;
        float s = 0.f;
        #pragma unroll
        for (int i = 0; i < 32; i++) s += Wx[X][d * 32 + i] * W_in[i * 3 + c];
        g_A[X][d][c] = s;
    }
    // c_X[d] = W_X[d] . b_in + b_X[d]   (96 entries)
    for (int idx = tid; idx < 96; idx += blockDim.x) {
        int X = idx / 32, d = idx % 32;
        float s = bx[X][d];
        #pragma unroll
        for (int i = 0; i < 32; i++) s += Wx[X][d * 32 + i] * b_in[i];
        g_c[X][d] = s;
    }
    __syncthreads();  // block-wide memory barrier: g_A/g_c visible

    // Stage 2: per-head folds. One thread per scalar.
    if (tid < 36) {                     // M
        int h = tid / 9, a = (tid / 3) % 3, b = tid % 3;
        float s = 0.f;
        #pragma unroll
        for (int j = 0; j < 8; j++)
            s += g_A[0][h * 8 + j][a] * g_A[1][h * 8 + j][b];
        g_P.M[h][a][b] = s;
    } else if (tid < 72) {              // G
        int t2 = tid - 36;
        int h = t2 / 9, o = (t2 / 3) % 3, c = t2 % 3;
        float s = 0.f;
        #pragma unroll
        for (int j = 0; j < 8; j++)
            s += W_o[o * 32 + h * 8 + j] * g_A[2][h * 8 + j][c];
        g_P.G[h][o][c] = s;
    } else if (tid < 84) {              // u
        int t2 = tid - 72;
        int h = t2 / 3, b = t2 % 3;
        float s = 0.f;
        #pragma unroll
        for (int j = 0; j < 8; j++)
            s += g_c[0][h * 8 + j] * g_A[1][h * 8 + j][b];
        g_P.u[h][b] = s;
    } else if (tid < 96) {              // r
        int t2 = tid - 84;
        int h = t2 / 3, a = t2 % 3;
        float s = 0.f;
        #pragma unroll
        for (int j = 0; j < 8; j++)
            s += g_A[0][h * 8 + j][a] * g_c[1][h * 8 + j];
        g_P.r[h][a] = s;
    } else if (tid < 100) {             // e
        int h = tid - 96;
        float s = 0.f;
        #pragma unroll
        for (int j = 0; j < 8; j++)
            s += g_c[0][h * 8 + j] * g_c[1][h * 8 + j];
        g_P.e[h] = s;
    } else if (tid < 112) {             // g
        int t2 = tid - 100;
        int h = t2 / 3, o = t2 % 3;
        float s = 0.f;
        #pragma unroll
        for (int j = 0; j < 8; j++)
            s += W_o[o * 32 + h * 8 + j] * g_c[2][h * 8 + j];
        g_P.g[h][o] = s;
    } else if (tid < 115) {             // bo
        g_P.bo[tid - 112] = b_o[tid - 112];
    }
}

// One thread per (b, h, w). Block of 256 threads covers a full W-row:
// all z loads / output stores are perfectly coalesced 128B lines.
__global__ __launch_bounds__(256, 6) void attn_main_kernel(
    const float* __restrict__ Z,   // (B=4, T=8, C=3, 256, 256)
    float* __restrict__ O)         // (B=4, 3, 256, 256)
{
    __shared__ DerivedParams sp;
    {
        const float* src = reinterpret_cast<const float*>(&g_P);
        float* dst = reinterpret_cast<float*>(&sp);
        if (threadIdx.x < (int)(sizeof(DerivedParams) / 4))
            dst[threadIdx.x] = src[threadIdx.x];
    }
    __syncthreads();

    const int idx = blockIdx.x * 256 + threadIdx.x;   // 0 .. 262143
    const int pix = idx & 65535;                      // h*256 + w
    const int b   = idx >> 16;
    const int plane = 65536;

    // Load the 24 input scalars for this position (stride = one HW plane).
    const int base = b * 24 * plane + pix;
    float z[8][3];
    #pragma unroll
    for (int t = 0; t < 8; t++)
        #pragma unroll
        for (int c = 0; c < 3; c++)
            z[t][c] = __ldg(&Z[base + (t * 3 + c) * plane]);

    float out0 = sp.bo[0], out1 = sp.bo[1], out2 = sp.bo[2];
    const float scale = 0.3535533905932738f;  // 1/sqrt(8)

    #pragma unroll
    for (int hd = 0; hd < 4; hd++) {
        // vq[b3] = u[b3] + sum_a z7[a] * M[a][b3]
        float vq0 = sp.u[hd][0] + z[7][0]*sp.M[hd][0][0] + z[7][1]*sp.M[hd][1][0] + z[7][2]*sp.M[hd][2][0];
        float vq1 = sp.u[hd][1] + z[7][0]*sp.M[hd][0][1] + z[7][1]*sp.M[hd][1][1] + z[7][2]*sp.M[hd][2][1];
        float vq2 = sp.u[hd][2] + z[7][0]*sp.M[hd][0][2] + z[7][1]*sp.M[hd][1][2] + z[7][2]*sp.M[hd][2][2];
        float rz  = sp.e[hd] + sp.r[hd][0]*z[7][0] + sp.r[hd][1]*z[7][1] + sp.r[hd][2]*z[7][2];

        float sc[8];
        float m = -1e30f;
        #pragma unroll
        for (int t = 0; t < 8; t++) {
            sc[t] = (rz + vq0 * z[t][0] + vq1 * z[t][1] + vq2 * z[t][2]) * scale;
            m = fmaxf(m, sc[t]);
        }
        float esum = 0.f;
        #pragma unroll
        for (int t = 0; t < 8; t++) {
            sc[t] = __expf(sc[t] - m);
            esum += sc[t];
        }
        const float inv = __fdividef(1.0f, esum);

        float zb0 = 0.f, zb1 = 0.f, zb2 = 0.f;
        #pragma unroll
        for (int t = 0; t < 8; t++) {
            zb0 += sc[t] * z[t][0];
            zb1 += sc[t] * z[t][1];
            zb2 += sc[t] * z[t][2];
        }
        zb0 *= inv; zb1 *= inv; zb2 *= inv;

        out0 += sp.g[hd][0] + sp.G[hd][0][0]*zb0 + sp.G[hd][0][1]*zb1 + sp.G[hd][0][2]*zb2;
        out1 += sp.g[hd][1] + sp.G[hd][1][0]*zb0 + sp.G[hd][1][1]*zb1 + sp.G[hd][1][2]*zb2;
        out2 += sp.g[hd][2] + sp.G[hd][2][0]*zb0 + sp.G[hd][2][1]*zb1 + sp.G[hd][2][2]*zb2;
    }

    const int obase = b * 3 * plane + pix;
    O[obase]             = out0;
    O[obase + plane]     = out1;
    O[obase + 2 * plane] = out2;
}

extern "C" void kernel_launch(void* const* d_in, const int* in_sizes, int n_in,
                              void* d_out, int out_size)
{
    const float* Z    = (const float*)d_in[0];
    const float* W_in = (const float*)d_in[1];
    const float* b_in = (const float*)d_in[2];
    const float* W_q  = (const float*)d_in[3];
    const float* b_q  = (const float*)d_in[4];
    const float* W_k  = (const float*)d_in[5];
    const float* b_k  = (const float*)d_in[6];
    const float* W_v  = (const float*)d_in[7];
    const float* b_v  = (const float*)d_in[8];
    const float* W_o  = (const float*)d_in[9];
    const float* b_o  = (const float*)d_in[10];

    precompute_kernel<<<1, 128>>>(W_in, b_in, W_q, b_q, W_k, b_k, W_v, b_v, W_o, b_o);

    // 262144 positions / 256 threads = 1024 blocks
    attn_main_kernel<<<1024, 256>>>(Z, (float*)d_out);
}

// round 6
// speedup vs baseline: 1.7826x; 1.7826x over previous
#include <cuda_runtime.h>
#include <cuda_bf16.h>

// ---------------------------------------------------------------------------
// Attention_26379689132660  — algebraically collapsed attention.
//
// Per spatial position everything is affine in the 3-channel inputs z_t, so
// the whole network folds into per-head 3x3 forms (see R3 derivation):
//   score_h(t) = SC * ( z7^T M_h z_t + u_h.z_t + r_h.z7 + e_h )
//   out        = b_o + sum_h ( G_h zbar_h + g_h ),  zbar_h = softmax-mean of z_t
// SC = (1/sqrt(dk)) * log2(e) is folded into M/u/r/e so the softmax is a raw
// exp2 (single MUFU.EX2).
//
// R4 change: 4 pixels per thread via float4 — 24 LDG.128 per thread instead
// of 24 LDG.32 per pixel. Cuts L1tex/issue overhead ~4x; kernel should drop
// from overhead-bound (23.7us) toward the mem/FMA floor (~5-9us).
// ---------------------------------------------------------------------------

struct DerivedParams {
    float M[4][3][3];   // per-head bilinear score matrix (pre-scaled by SC)
    float u[4][3];      // pre-scaled
    float r[4][3];      // pre-scaled
    float e[4];         // pre-scaled
    float G[4][3][3];   // per-head fused output matrix
    float g[4][3];
    float bo[3];
};
// 115 floats

__device__ float g_A[3][32][3];   // A_q, A_k, A_v
__device__ float g_c[3][32];      // c_q, c_k, c_v
__device__ DerivedParams g_P;

// SC = (1/sqrt(8)) * log2(e): folded into score-domain params.
#define SC_FOLD (0.3535533905932738f * 1.4426950408889634f)

__global__ void precompute_kernel(
    const float* __restrict__ W_in, const float* __restrict__ b_in,
    const float* __restrict__ W_q,  const float* __restrict__ b_q,
    const float* __restrict__ W_k,  const float* __restrict__ b_k,
    const float* __restrict__ W_v,  const float* __restrict__ b_v,
    const float* __restrict__ W_o,  const float* __restrict__ b_o)
{
    const int tid = threadIdx.x;
    const float* Wx[3] = {W_q, W_k, W_v};
    const float* bx[3] = {b_q, b_k, b_v};

    // A_X[d][c] = sum_i W_X[d][i] * W_in[i][c]
    for (int idx = tid; idx < 288; idx += blockDim.x) {
        int X = idx / 96, rem = idx % 96, d = rem / 3, c = rem % 3;
        float s = 0.f;
        #pragma unroll
        for (int i = 0; i < 32; i++) s += Wx[X][d * 32 + i] * W_in[i * 3 + c];
        g_A[X][d][c] = s;
    }
    // c_X[d] = W_X[d] . b_in + b_X[d]
    for (int idx = tid; idx < 96; idx += blockDim.x) {
        int X = idx / 32, d = idx % 32;
        float s = bx[X][d];
        #pragma unroll
        for (int i = 0; i < 32; i++) s += Wx[X][d * 32 + i] * b_in[i];
        g_c[X][d] = s;
    }
    __syncthreads();

    if (tid < 36) {                     // M  (score-domain: fold SC)
        int h = tid / 9, a = (tid / 3) % 3, b = tid % 3;
        float s = 0.f;
        #pragma unroll
        for (int j = 0; j < 8; j++)
            s += g_A[0][h * 8 + j][a] * g_A[1][h * 8 + j][b];
        g_P.M[h][a][b] = s * SC_FOLD;
    } else if (tid < 72) {              // G
        int t2 = tid - 36;
        int h = t2 / 9, o = (t2 / 3) % 3, c = t2 % 3;
        float s = 0.f;
        #pragma unroll
        for (int j = 0; j < 8; j++)
            s += W_o[o * 32 + h * 8 + j] * g_A[2][h * 8 + j][c];
        g_P.G[h][o][c] = s;
    } else if (tid < 84) {              // u  (fold SC)
        int t2 = tid - 72;
        int h = t2 / 3, b = t2 % 3;
        float s = 0.f;
        #pragma unroll
        for (int j = 0; j < 8; j++)
            s += g_c[0][h * 8 + j] * g_A[1][h * 8 + j][b];
        g_P.u[h][b] = s * SC_FOLD;
    } else if (tid < 96) {              // r  (fold SC)
        int t2 = tid - 84;
        int h = t2 / 3, a = t2 % 3;
        float s = 0.f;
        #pragma unroll
        for (int j = 0; j < 8; j++)
            s += g_A[0][h * 8 + j][a] * g_c[1][h * 8 + j];
        g_P.r[h][a] = s * SC_FOLD;
    } else if (tid < 100) {             // e  (fold SC)
        int h = tid - 96;
        float s = 0.f;
        #pragma unroll
        for (int j = 0; j < 8; j++)
            s += g_c[0][h * 8 + j] * g_c[1][h * 8 + j];
        g_P.e[h] = s * SC_FOLD;
    } else if (tid < 112) {             // g
        int t2 = tid - 100;
        int h = t2 / 3, o = t2 % 3;
        float s = 0.f;
        #pragma unroll
        for (int j = 0; j < 8; j++)
            s += W_o[o * 32 + h * 8 + j] * g_c[2][h * 8 + j];
        g_P.g[h][o] = s;
    } else if (tid < 115) {             // bo
        g_P.bo[tid - 112] = b_o[tid - 112];
    }
}

// 4 pixels per thread (float4). 128 threads/block = 512 consecutive pixels
// (= 2 full W-rows) per block -> all loads/stores perfectly coalesced 128B.
__global__ __launch_bounds__(128) void attn_main_kernel(
    const float4* __restrict__ Z,   // (B=4, T=8, C=3, 256, 256) as float4
    float4* __restrict__ O)         // (B=4, 3, 256, 256) as float4
{
    __shared__ DerivedParams sp;
    {
        const float* src = reinterpret_cast<const float*>(&g_P);
        float* dst = reinterpret_cast<float*>(&sp);
        if (threadIdx.x < (int)(sizeof(DerivedParams) / 4))
            dst[threadIdx.x] = src[threadIdx.x];
    }
    __syncthreads();

    const int plane4 = 256 * 256 / 4;               // 16384 float4 per plane
    const int gid = blockIdx.x * 128 + threadIdx.x; // 0..65535 pixel-groups
    const int b = gid >> 14;                        // batch
    const int g = gid & 16383;                      // float4 index in plane

    // Load 24 float4 (4 pixels x 8 tokens x 3 channels), all independent.
    const int base = b * 24 * plane4 + g;
    float zz[4][8][3];
    #pragma unroll
    for (int t = 0; t < 8; t++) {
        #pragma unroll
        for (int c = 0; c < 3; c++) {
            float4 v = __ldg(&Z[base + (t * 3 + c) * plane4]);
            zz[0][t][c] = v.x;
            zz[1][t][c] = v.y;
            zz[2][t][c] = v.z;
            zz[3][t][c] = v.w;
        }
    }

    float out[4][3];
    #pragma unroll
    for (int p = 0; p < 4; p++) {
        out[p][0] = sp.bo[0];
        out[p][1] = sp.bo[1];
        out[p][2] = sp.bo[2];
    }

    #pragma unroll
    for (int hd = 0; hd < 4; hd++) {
        #pragma unroll
        for (int p = 0; p < 4; p++) {
            const float z70 = zz[p][7][0], z71 = zz[p][7][1], z72 = zz[p][7][2];
            // score-domain (already includes SC = scale*log2e):
            // vq = u + z7^T M ; rz = e + r.z7
            float vq0 = sp.u[hd][0] + z70*sp.M[hd][0][0] + z71*sp.M[hd][1][0] + z72*sp.M[hd][2][0];
            float vq1 = sp.u[hd][1] + z70*sp.M[hd][0][1] + z71*sp.M[hd][1][1] + z72*sp.M[hd][2][1];
            float vq2 = sp.u[hd][2] + z70*sp.M[hd][0][2] + z71*sp.M[hd][1][2] + z72*sp.M[hd][2][2];
            float rz  = sp.e[hd] + sp.r[hd][0]*z70 + sp.r[hd][1]*z71 + sp.r[hd][2]*z72;

            float sc[8];
            float m = -1e30f;
            #pragma unroll
            for (int t = 0; t < 8; t++) {
                sc[t] = rz + vq0 * zz[p][t][0] + vq1 * zz[p][t][1] + vq2 * zz[p][t][2];
                m = fmaxf(m, sc[t]);
            }
            float esum = 0.f;
            #pragma unroll
            for (int t = 0; t < 8; t++) {
                sc[t] = exp2f(sc[t] - m);   // MUFU.EX2
                esum += sc[t];
            }
            const float inv = __fdividef(1.0f, esum);

            float zb0 = 0.f, zb1 = 0.f, zb2 = 0.f;
            #pragma unroll
            for (int t = 0; t < 8; t++) {
                zb0 += sc[t] * zz[p][t][0];
                zb1 += sc[t] * zz[p][t][1];
                zb2 += sc[t] * zz[p][t][2];
            }
            zb0 *= inv; zb1 *= inv; zb2 *= inv;

            out[p][0] += sp.g[hd][0] + sp.G[hd][0][0]*zb0 + sp.G[hd][0][1]*zb1 + sp.G[hd][0][2]*zb2;
            out[p][1] += sp.g[hd][1] + sp.G[hd][1][0]*zb0 + sp.G[hd][1][1]*zb1 + sp.G[hd][1][2]*zb2;
            out[p][2] += sp.g[hd][2] + sp.G[hd][2][0]*zb0 + sp.G[hd][2][1]*zb1 + sp.G[hd][2][2]*zb2;
        }
    }

    const int obase = b * 3 * plane4 + g;
    #pragma unroll
    for (int ch = 0; ch < 3; ch++)
        O[obase + ch * plane4] =
            make_float4(out[0][ch], out[1][ch], out[2][ch], out[3][ch]);
}

extern "C" void kernel_launch(void* const* d_in, const int* in_sizes, int n_in,
                              void* d_out, int out_size)
{
    const float* Z    = (const float*)d_in[0];
    const float* W_in = (const float*)d_in[1];
    const float* b_in = (const float*)d_in[2];
    const float* W_q  = (const float*)d_in[3];
    const float* b_q  = (const float*)d_in[4];
    const float* W_k  = (const float*)d_in[5];
    const float* b_k  = (const float*)d_in[6];
    const float* W_v  = (const float*)d_in[7];
    const float* b_v  = (const float*)d_in[8];
    const float* W_o  = (const float*)d_in[9];
    const float* b_o  = (const float*)d_in[10];

    precompute_kernel<<<1, 128>>>(W_in, b_in, W_q, b_q, W_k, b_k, W_v, b_v, W_o, b_o);

    // 262144 pixels / 4 per thread / 128 per block = 512 blocks
    attn_main_kernel<<<512, 128>>>((const float4*)Z, (float4*)d_out);
}